// round 1
// baseline (speedup 1.0000x reference)
#include <cuda_runtime.h>
#include <math.h>

#define NB   4
#define CC   256
#define HH   128
#define WW   128
#define NPIX (HH*WW)          // 16384 pixels per plane
#define NPIX_TOT (NB*NPIX)    // 65536
#define NPTS 5
#define G    3                // channel planes per CTA in smem (3*64KB = 192KB)
#define CG   ((CC + G - 1) / G)   // 86 channel-groups
#define SCALE 0.125f

// Precomputed per-(n,h,w,point) sampling table (channel-invariant).
// off = y_low*W + x_low (or -1 if invalid), lx/ly = fractional weights.
__device__ int   g_off[NPTS][NPIX_TOT];
__device__ float g_lx [NPTS][NPIX_TOT];
__device__ float g_ly [NPTS][NPIX_TOT];

__global__ void FR_precompute_kernel(const float* __restrict__ bb) {
    int i = blockIdx.x * blockDim.x + threadIdx.x;
    if (i >= NPIX_TOT) return;
    const float* b = bb + (size_t)i * 5;
    float cx = b[0], cy = b[1], w = b[2], h = b[3], t = b[4];
    float st, ct;
    sincosf(t, &st, &ct);
    float vx =  w * ct * 0.5f, vy = w * st * 0.5f;
    float wx = -h * st * 0.5f, wy = h * ct * 0.5f;

    float pxs[NPTS] = {cx, cx + vx + wx, cx - vx + wx, cx - vx - wx, cx + vx - wx};
    float pys[NPTS] = {cy, cy + vy + wy, cy - vy + wy, cy - vy - wy, cy + vy - wy};

#pragma unroll
    for (int p = 0; p < NPTS; p++) {
        float x = pxs[p] * SCALE;
        float y = pys[p] * SCALE;
        bool valid = (y >= -1.0f) && (y <= (float)HH) && (x >= -1.0f) && (x <= (float)WW);
        y = fmaxf(y, 0.0f);
        x = fmaxf(x, 0.0f);
        int yl = min((int)floorf(y), HH - 1);
        int xl = min((int)floorf(x), WW - 1);
        if (yl >= HH - 1) y = (float)yl;   // snap onto last row/col (mmcv border rule)
        if (xl >= WW - 1) x = (float)xl;
        float ly = y - (float)yl;
        float lx = x - (float)xl;
        int off = yl * WW + xl;
        g_off[p][i] = valid ? off : -1;
        g_lx [p][i] = lx;
        g_ly [p][i] = ly;
    }
}

// One CTA per (batch, group of G channels). Planes staged in smem; all 20
// gathers per pixel per channel served from shared memory.
__global__ __launch_bounds__(512, 1)
void FR_refine_kernel(const float* __restrict__ feat, float* __restrict__ out) {
    extern __shared__ float sp[];  // [G][NPIX]
    int bx = blockIdx.x;
    int n  = bx / CG;
    int c0 = (bx % CG) * G;
    int gn = min(G, CC - c0);      // 256 = 3*85 + 1 -> one tail CTA per batch

    // Cooperative load of gn contiguous channel planes into smem (float4).
    const float4* src = (const float4*)(feat + ((size_t)n * CC + c0) * NPIX);
    float4* dst = (float4*)sp;
    int nv = gn * (NPIX / 4);
    for (int i = threadIdx.x; i < nv; i += blockDim.x) dst[i] = src[i];
    __syncthreads();

    int tbase = n * NPIX;
    for (int pix = threadIdx.x; pix < NPIX; pix += blockDim.x) {
        int ti = tbase + pix;

        int   o00[NPTS], o01[NPTS], o10[NPTS], o11[NPTS];
        float wll[NPTS], wlh[NPTS], whl[NPTS], whh[NPTS];
#pragma unroll
        for (int p = 0; p < NPTS; p++) {
            int   off = g_off[p][ti];
            float lx  = g_lx [p][ti];
            float ly  = g_ly [p][ti];
            float vf  = (off >= 0) ? 1.0f : 0.0f;
            off = max(off, 0);
            int xl = off & (WW - 1);
            int yl = off >> 7;               // WW == 128
            int dx = (xl < WW - 1) ? 1  : 0;
            int dy = (yl < HH - 1) ? WW : 0;
            float hx = 1.0f - lx;
            float hy = 1.0f - ly;
            wll[p] = vf * hy * hx;
            wlh[p] = vf * hy * lx;
            whl[p] = vf * ly * hx;
            whh[p] = vf * ly * lx;
            o00[p] = off;
            o01[p] = off + dx;
            o10[p] = off + dy;
            o11[p] = off + dy + dx;
        }

        for (int g = 0; g < gn; g++) {
            const float* s = sp + g * NPIX;
            float acc = s[pix];              // residual add, straight from smem
#pragma unroll
            for (int p = 0; p < NPTS; p++) {
                acc += wll[p] * s[o00[p]];
                acc += wlh[p] * s[o01[p]];
                acc += whl[p] * s[o10[p]];
                acc += whh[p] * s[o11[p]];
            }
            out[((size_t)n * CC + c0 + g) * NPIX + pix] = acc;
        }
    }
}

extern "C" void kernel_launch(void* const* d_in, const int* in_sizes, int n_in,
                              void* d_out, int out_size) {
    const float* feat = (const float*)d_in[0];  // [4,256,128,128] f32
    const float* bb   = (const float*)d_in[1];  // [4,128,128,5]   f32
    float*       out  = (float*)d_out;          // [4,256,128,128] f32

    FR_precompute_kernel<<<(NPIX_TOT + 255) / 256, 256>>>(bb);

    size_t smem = (size_t)G * NPIX * sizeof(float);   // 196608 B
    cudaFuncSetAttribute(FR_refine_kernel,
                         cudaFuncAttributeMaxDynamicSharedMemorySize, (int)smem);
    FR_refine_kernel<<<NB * CG, 512, smem>>>(feat, out);
}

// round 3
// speedup vs baseline: 2.0520x; 2.0520x over previous
#include <cuda_runtime.h>
#include <cuda_fp16.h>
#include <math.h>

#define NB   4
#define CC   256
#define HH   128
#define WW   128
#define NPIX (HH*WW)            // 16384
#define NPIX_TOT (NB*NPIX)      // 65536
#define NPTS 5
#define G    4                  // channels per CTA, interleaved half4 in smem (128 KB)
#define CG   (CC / G)           // 64 channel-groups per batch
#define SCALE 0.125f

static __device__ __forceinline__ unsigned pack_h2(float a, float b) {
    half2 h = __floats2half2_rn(a, b);
    return *reinterpret_cast<unsigned*>(&h);
}
static __device__ __forceinline__ float2 unpack_h2(unsigned u) {
    half2 h = *reinterpret_cast<half2*>(&u);
    return __half22float2(h);
}

// Packed per-(n,h,w,point) table: x = y_low*W+x_low (or -1 invalid), y = half2(lx, ly)
__device__ int2 g_tab[NPTS][NPIX_TOT];

__global__ void FR_precompute_kernel(const float* __restrict__ bb) {
    int i = blockIdx.x * blockDim.x + threadIdx.x;
    if (i >= NPIX_TOT) return;
    const float* b = bb + (size_t)i * 5;
    float cx = b[0], cy = b[1], w = b[2], h = b[3], t = b[4];
    float st, ct;
    sincosf(t, &st, &ct);
    float vx =  w * ct * 0.5f, vy = w * st * 0.5f;
    float wx = -h * st * 0.5f, wy = h * ct * 0.5f;

    float pxs[NPTS] = {cx, cx + vx + wx, cx - vx + wx, cx - vx - wx, cx + vx - wx};
    float pys[NPTS] = {cy, cy + vy + wy, cy - vy + wy, cy - vy - wy, cy + vy - wy};

#pragma unroll
    for (int p = 0; p < NPTS; p++) {
        float x = pxs[p] * SCALE;
        float y = pys[p] * SCALE;
        bool valid = (y >= -1.0f) && (y <= (float)HH) && (x >= -1.0f) && (x <= (float)WW);
        y = fmaxf(y, 0.0f);
        x = fmaxf(x, 0.0f);
        int yl = min((int)floorf(y), HH - 1);
        int xl = min((int)floorf(x), WW - 1);
        if (yl >= HH - 1) y = (float)yl;   // mmcv border rule
        if (xl >= WW - 1) x = (float)xl;
        float ly = y - (float)yl;
        float lx = x - (float)xl;
        int off = yl * WW + xl;
        int2 e;
        e.x = valid ? off : -1;
        e.y = (int)pack_h2(lx, ly);
        g_tab[p][i] = e;
    }
}

// One CTA per (batch, quad of channels). 4 channels staged interleaved as half4
// per pixel; every gather is one LDS.64 serving 4 channels.
__global__ __launch_bounds__(1024, 1)
void FR_refine_kernel(const float* __restrict__ feat, float* __restrict__ out) {
    extern __shared__ unsigned int smem_raw[];
    uint2* sq = (uint2*)smem_raw;              // [NPIX] x packed half4

    int bx = blockIdx.x;
    int n  = bx / CG;
    int c0 = (bx % CG) * G;
    const float* f0 = feat + ((size_t)n * CC + c0) * NPIX;

    // Fill: per pixel, gather 4 channels (coalesced per-plane LDG), pack half4,
    // one conflict-free STS.64.
    for (int p = threadIdx.x; p < NPIX; p += blockDim.x) {
        float v0 = f0[p];
        float v1 = f0[p + NPIX];
        float v2 = f0[p + 2*NPIX];
        float v3 = f0[p + 3*NPIX];
        uint2 pk;
        pk.x = pack_h2(v0, v1);
        pk.y = pack_h2(v2, v3);
        sq[p] = pk;
    }
    __syncthreads();

    int tbase = n * NPIX;
    for (int pix = threadIdx.x; pix < NPIX; pix += blockDim.x) {
        // residual term read in full fp32 from gmem (exact identity pass-through)
        float a0 = f0[pix];
        float a1 = f0[pix + NPIX];
        float a2 = f0[pix + 2*NPIX];
        float a3 = f0[pix + 3*NPIX];

#pragma unroll
        for (int p = 0; p < NPTS; p++) {
            int2 t = g_tab[p][tbase + pix];
            float vf = (t.x >= 0) ? 1.0f : 0.0f;
            int off = max(t.x, 0);
            float2 l = unpack_h2((unsigned)t.y);
            float lx = l.x;
            float ly = l.y;
            int xl = off & (WW - 1);
            int yl = off >> 7;
            int dx  = (xl < WW - 1) ? 1  : 0;
            int dyw = (yl < HH - 1) ? WW : 0;
            float hx = 1.0f - lx, hy = 1.0f - ly;
            float w00 = vf * hy * hx;
            float w01 = vf * hy * lx;
            float w10 = vf * ly * hx;
            float w11 = vf * ly * lx;

            int o00 = off, o01 = off + dx, o10 = off + dyw, o11 = off + dyw + dx;

            uint2 v;
            float2 c01, c23;
            v = sq[o00];
            c01 = unpack_h2(v.x); c23 = unpack_h2(v.y);
            a0 += w00 * c01.x; a1 += w00 * c01.y; a2 += w00 * c23.x; a3 += w00 * c23.y;
            v = sq[o01];
            c01 = unpack_h2(v.x); c23 = unpack_h2(v.y);
            a0 += w01 * c01.x; a1 += w01 * c01.y; a2 += w01 * c23.x; a3 += w01 * c23.y;
            v = sq[o10];
            c01 = unpack_h2(v.x); c23 = unpack_h2(v.y);
            a0 += w10 * c01.x; a1 += w10 * c01.y; a2 += w10 * c23.x; a3 += w10 * c23.y;
            v = sq[o11];
            c01 = unpack_h2(v.x); c23 = unpack_h2(v.y);
            a0 += w11 * c01.x; a1 += w11 * c01.y; a2 += w11 * c23.x; a3 += w11 * c23.y;
        }

        float* op = out + ((size_t)n * CC + c0) * NPIX + pix;
        op[0]        = a0;
        op[NPIX]     = a1;
        op[2*NPIX]   = a2;
        op[3*NPIX]   = a3;
    }
}

extern "C" void kernel_launch(void* const* d_in, const int* in_sizes, int n_in,
                              void* d_out, int out_size) {
    const float* feat = (const float*)d_in[0];  // [4,256,128,128] f32
    const float* bb   = (const float*)d_in[1];  // [4,128,128,5]   f32
    float*       out  = (float*)d_out;          // [4,256,128,128] f32

    FR_precompute_kernel<<<(NPIX_TOT + 255) / 256, 256>>>(bb);

    size_t smem = (size_t)NPIX * 8;   // 131072 B
    cudaFuncSetAttribute(FR_refine_kernel,
                         cudaFuncAttributeMaxDynamicSharedMemorySize, (int)smem);
    FR_refine_kernel<<<NB * CG, 1024, smem>>>(feat, out);
}